// round 2
// baseline (speedup 1.0000x reference)
#include <cuda_runtime.h>

// Tiny transformer block, one warp per batch item.
// T=8 tokens, C=32 embed, 4 heads x 8 head-dim, FF=128.
//
// All weights live in shared memory, transposed ([out_col][k]) and
// chunk-XOR-swizzled so per-column float4 reads are bank-conflict free.
// Per-warp activation scratch uses padded strides (36 / 100 / 132) so
// broadcast float4 reads across t are conflict-free.

#define TT 8
#define CC 32
#define FF2K 128

// shared memory layout (in floats)
#define OFF_WQKV  0        // 96 cols x 32 k  = 3072
#define OFF_WPROJ 3072     // 32 x 32         = 1024
#define OFF_WFF1  4096     // 128 x 32        = 4096
#define OFF_WFF2  8192     // 32 x 128        = 4096
#define OFF_WARP  12288
#define WARP_FLOATS 1664   // per-warp scratch
// per-warp scratch layout:
#define OFF_XS 0           // [8][36]
#define OFF_YS 288         // [8][36]
#define OFF_SC 576         // 1088-float union: {qkv[8][100], a[8][36]} then H[8][132]
#define SMEM_FLOATS (12288 + 8 * 1664)   // 25600 floats = 100 KB

__device__ __forceinline__ int swz(int k, int col) {
    // chunk-XOR swizzle: keeps 4-float chunks contiguous, rotates chunk slot
    return ((((k >> 2) ^ (col & 7)) << 2) | (k & 3));
}

__device__ __forceinline__ float dot4fma(float4 x, float4 w, float acc) {
    acc = fmaf(x.x, w.x, acc);
    acc = fmaf(x.y, w.y, acc);
    acc = fmaf(x.z, w.z, acc);
    acc = fmaf(x.w, w.w, acc);
    return acc;
}

__global__ void __launch_bounds__(256, 2)
block_kernel(const float* __restrict__ Xg,
             const float* __restrict__ Wattn,   // [4][32][24]
             const float* __restrict__ Wproj,   // [32][32] (in,out)
             const float* __restrict__ Wff1,    // [32][128]
             const float* __restrict__ Wff2,    // [128][32]
             float* __restrict__ Out,
             int b)
{
    extern __shared__ float sm[];
    const int tid = threadIdx.x;

    // ---- stage weights (transposed + swizzled), once per block ----
    for (int idx = tid; idx < 96 * 32; idx += 256) {
        int col = idx >> 5, k = idx & 31;
        int h = col / 24, d = col - h * 24;         // col = h*24 + d
        sm[OFF_WQKV + col * 32 + swz(k, col)] = Wattn[h * 768 + k * 24 + d];
    }
    for (int idx = tid; idx < 32 * 32; idx += 256) {
        int col = idx >> 5, k = idx & 31;
        sm[OFF_WPROJ + col * 32 + swz(k, col)] = Wproj[k * 32 + col];
    }
    for (int idx = tid; idx < 128 * 32; idx += 256) {
        int col = idx >> 5, k = idx & 31;
        sm[OFF_WFF1 + col * 32 + swz(k, col)] = Wff1[k * 128 + col];
    }
    for (int idx = tid; idx < 32 * 128; idx += 256) {
        int col = idx >> 7, k = idx & 127;
        sm[OFF_WFF2 + col * 128 + swz(k, col)] = Wff2[k * 32 + col];
    }
    __syncthreads();

    const int warp = tid >> 5;
    const int lane = tid & 31;
    float* ws = sm + OFF_WARP + warp * WARP_FLOATS;
    float* Xs = ws + OFF_XS;   // [8][36]
    float* Ys = ws + OFF_YS;   // [8][36]
    float* SC = ws + OFF_SC;   // scratch union

    const int nwarps = (gridDim.x * blockDim.x) >> 5;
    for (int it = (blockIdx.x * blockDim.x + tid) >> 5; it < b; it += nwarps) {

        // ---- load X (8x32) into Xs, stride 36 ----
        const float4* Xi = (const float4*)(Xg + (size_t)it * 256);
        #pragma unroll
        for (int r = 0; r < 2; r++) {
            int e4 = lane + 32 * r;               // float4 index 0..63
            float4 v = Xi[e4];
            int t = e4 >> 3, k4 = (e4 & 7) << 2;
            *(float4*)&Xs[t * 36 + k4] = v;
        }
        __syncwarp();

        // ---- fused QKV: X(8x32) @ Wcat(32x96); lane owns cols lane, lane+32, lane+64 ----
        {
            float acc[8][3];
            #pragma unroll
            for (int t = 0; t < 8; t++) { acc[t][0] = 0.f; acc[t][1] = 0.f; acc[t][2] = 0.f; }
            const float* Wq = sm + OFF_WQKV;
            const int sw7 = lane & 7;
            #pragma unroll
            for (int kc = 0; kc < 8; kc++) {
                const int cs = ((kc ^ sw7) << 2);
                float4 w0 = *(const float4*)&Wq[(lane      ) * 32 + cs];
                float4 w1 = *(const float4*)&Wq[(lane + 32 ) * 32 + cs];
                float4 w2 = *(const float4*)&Wq[(lane + 64 ) * 32 + cs];
                #pragma unroll
                for (int t = 0; t < 8; t++) {
                    float4 x = *(const float4*)&Xs[t * 36 + (kc << 2)];
                    acc[t][0] = dot4fma(x, w0, acc[t][0]);
                    acc[t][1] = dot4fma(x, w1, acc[t][1]);
                    acc[t][2] = dot4fma(x, w2, acc[t][2]);
                }
            }
            float* qk = SC;   // [8][100], col = h*24+d (K:0-7, Q:8-15, V:16-23)
            #pragma unroll
            for (int t = 0; t < 8; t++) {
                qk[t * 100 + lane      ] = acc[t][0];
                qk[t * 100 + lane + 32 ] = acc[t][1];
                qk[t * 100 + lane + 64 ] = acc[t][2];
            }
        }
        __syncwarp();

        // ---- attention: lane = h*8 + t1 ----
        {
            const int h = lane >> 3, t1 = lane & 7;
            const float* base = SC + h * 24;
            float4 q0 = *(const float4*)&base[t1 * 100 + 8];
            float4 q1 = *(const float4*)&base[t1 * 100 + 12];
            float s[8];
            float m = -1e30f;
            #pragma unroll
            for (int t2 = 0; t2 < 8; t2++) {
                float4 k0 = *(const float4*)&base[t2 * 100];
                float4 k1 = *(const float4*)&base[t2 * 100 + 4];
                float d = q0.x * k0.x + q0.y * k0.y + q0.z * k0.z + q0.w * k0.w
                        + q1.x * k1.x + q1.y * k1.y + q1.z * k1.z + q1.w * k1.w;
                d *= 0.17677669529663687f;          // 32^-0.5 (full embed dim, as in ref)
                d = (t2 <= t1) ? d : -1e30f;        // causal
                s[t2] = d;
                m = fmaxf(m, d);
            }
            float sum = 0.f;
            #pragma unroll
            for (int t2 = 0; t2 < 8; t2++) {
                float e = __expf(s[t2] - m);
                e = (t2 <= t1) ? e : 0.f;
                s[t2] = e;
                sum += e;
            }
            float inv = __fdividef(1.f, sum);
            float a[8];
            #pragma unroll
            for (int d = 0; d < 8; d++) a[d] = 0.f;
            #pragma unroll
            for (int t2 = 0; t2 < 8; t2++) {
                float wt = s[t2];
                float4 v0 = *(const float4*)&base[t2 * 100 + 16];
                float4 v1 = *(const float4*)&base[t2 * 100 + 20];
                a[0] = fmaf(wt, v0.x, a[0]); a[1] = fmaf(wt, v0.y, a[1]);
                a[2] = fmaf(wt, v0.z, a[2]); a[3] = fmaf(wt, v0.w, a[3]);
                a[4] = fmaf(wt, v1.x, a[4]); a[5] = fmaf(wt, v1.y, a[5]);
                a[6] = fmaf(wt, v1.z, a[6]); a[7] = fmaf(wt, v1.w, a[7]);
            }
            float* as_ = SC + 800;   // [8][36], concat layout [t][h*8+d]
            float4 o0 = make_float4(a[0] * inv, a[1] * inv, a[2] * inv, a[3] * inv);
            float4 o1 = make_float4(a[4] * inv, a[5] * inv, a[6] * inv, a[7] * inv);
            *(float4*)&as_[t1 * 36 + h * 8    ] = o0;
            *(float4*)&as_[t1 * 36 + h * 8 + 4] = o1;
        }
        __syncwarp();

        // ---- proj + residual: Y = X + A @ Wproj; lane = out col ----
        {
            const float* as_ = SC + 800;
            const float* Wp = sm + OFF_WPROJ;
            const int sw7 = lane & 7;
            float acc[8];
            #pragma unroll
            for (int t = 0; t < 8; t++) acc[t] = Xs[t * 36 + lane];
            #pragma unroll
            for (int kc = 0; kc < 8; kc++) {
                float4 w = *(const float4*)&Wp[lane * 32 + ((kc ^ sw7) << 2)];
                #pragma unroll
                for (int t = 0; t < 8; t++) {
                    float4 x = *(const float4*)&as_[t * 36 + (kc << 2)];
                    acc[t] = dot4fma(x, w, acc[t]);
                }
            }
            #pragma unroll
            for (int t = 0; t < 8; t++) Ys[t * 36 + lane] = acc[t];
        }
        __syncwarp();

        // ---- FF1: H = relu(Y @ Wff1); lane owns cols lane+32j ----
        float* Hs = SC;   // [8][132], overwrites qkv/a scratch (dead)
        {
            const float* W1 = sm + OFF_WFF1;
            const int sw7 = lane & 7;
            float f[8][4];
            #pragma unroll
            for (int t = 0; t < 8; t++) {
                f[t][0] = 0.f; f[t][1] = 0.f; f[t][2] = 0.f; f[t][3] = 0.f;
            }
            #pragma unroll
            for (int kc = 0; kc < 8; kc++) {
                const int cs = ((kc ^ sw7) << 2);
                float4 w0 = *(const float4*)&W1[(lane      ) * 32 + cs];
                float4 w1 = *(const float4*)&W1[(lane + 32 ) * 32 + cs];
                float4 w2 = *(const float4*)&W1[(lane + 64 ) * 32 + cs];
                float4 w3 = *(const float4*)&W1[(lane + 96 ) * 32 + cs];
                #pragma unroll
                for (int t = 0; t < 8; t++) {
                    float4 x = *(const float4*)&Ys[t * 36 + (kc << 2)];
                    f[t][0] = dot4fma(x, w0, f[t][0]);
                    f[t][1] = dot4fma(x, w1, f[t][1]);
                    f[t][2] = dot4fma(x, w2, f[t][2]);
                    f[t][3] = dot4fma(x, w3, f[t][3]);
                }
            }
            #pragma unroll
            for (int t = 0; t < 8; t++) {
                Hs[t * 132 + lane      ] = fmaxf(f[t][0], 0.f);
                Hs[t * 132 + lane + 32 ] = fmaxf(f[t][1], 0.f);
                Hs[t * 132 + lane + 64 ] = fmaxf(f[t][2], 0.f);
                Hs[t * 132 + lane + 96 ] = fmaxf(f[t][3], 0.f);
            }
        }
        __syncwarp();

        // ---- FF2 + residual + store: out = Y + H @ Wff2 ----
        {
            const float* W2 = sm + OFF_WFF2;
            const int sw7 = lane & 7;
            float acc[8];
            #pragma unroll
            for (int t = 0; t < 8; t++) acc[t] = Ys[t * 36 + lane];
            #pragma unroll
            for (int jc = 0; jc < 32; jc++) {
                float4 w = *(const float4*)&W2[lane * 128 + ((jc ^ sw7) << 2)];
                #pragma unroll
                for (int t = 0; t < 8; t++) {
                    float4 hv = *(const float4*)&Hs[t * 132 + (jc << 2)];
                    acc[t] = dot4fma(hv, w, acc[t]);
                }
            }
            float* Og = Out + (size_t)it * 256;
            #pragma unroll
            for (int t = 0; t < 8; t++) Og[t * 32 + lane] = acc[t];
        }
        __syncwarp();   // scratch reused next iteration
    }
}

extern "C" void kernel_launch(void* const* d_in, const int* in_sizes, int n_in,
                              void* d_out, int out_size) {
    const float* X     = (const float*)d_in[0];
    const float* Wattn = (const float*)d_in[1];
    const float* Wproj = (const float*)d_in[2];
    const float* Wff1  = (const float*)d_in[3];
    const float* Wff2  = (const float*)d_in[4];
    float* out = (float*)d_out;

    int b = in_sizes[0] / 256;           // items = elements / (T*C)
    int smem_bytes = SMEM_FLOATS * (int)sizeof(float);   // 102400

    cudaFuncSetAttribute(block_kernel,
                         cudaFuncAttributeMaxDynamicSharedMemorySize, smem_bytes);

    int blocks = (b + 7) / 8;            // one item per warp, 8 warps/block
    block_kernel<<<blocks, 256, smem_bytes>>>(X, Wattn, Wproj, Wff1, Wff2, out, b);
    (void)n_in; (void)out_size;
}

// round 4
// speedup vs baseline: 8.6046x; 8.6046x over previous
#include <cuda_runtime.h>
#include <cuda_bf16.h>
#include <cstdint>

// Tiny transformer block via warp-level bf16 HMMA (mma.sync m16n8k16).
// One warp = 16 tokens (2 items) per iteration. Activations live in registers
// in fragment-native layout; only qkv results + attention outputs touch smem.

// smem layout (bytes), per CTA:
//   WQ  [96 n][40 bf16]  : 7680     (stride 80B, conflict-free frag loads)
//   WP  [32 n][40 bf16]  : 2560
//   W1  [128n][40 bf16]  : 10240
//   W2  [32 n][136 bf16] : 8704     (stride 272B)
//   per-warp (x8): qkv f32 [16][100] = 6400 ; attn bf16 [16][40] = 1280
#define OFF_WQ 0
#define OFF_WP 7680
#define OFF_W1 10240
#define OFF_W2 20480
#define OFF_WARP 29184
#define WARP_BYTES 7680
#define SMEM_BYTES (OFF_WARP + 8 * WARP_BYTES)   // 90624

static __device__ __forceinline__ uint32_t cvt_bf2(float lo, float hi) {
    uint32_t r;
    asm("cvt.rn.bf16x2.f32 %0, %1, %2;" : "=r"(r) : "f"(hi), "f"(lo));
    return r;
}

static __device__ __forceinline__ void mma16816(float& d0, float& d1, float& d2, float& d3,
                                                uint32_t a0, uint32_t a1, uint32_t a2, uint32_t a3,
                                                uint32_t b0, uint32_t b1) {
    asm volatile("mma.sync.aligned.m16n8k16.row.col.f32.bf16.bf16.f32 "
                 "{%0,%1,%2,%3}, {%4,%5,%6,%7}, {%8,%9}, {%0,%1,%2,%3};"
                 : "+f"(d0), "+f"(d1), "+f"(d2), "+f"(d3)
                 : "r"(a0), "r"(a1), "r"(a2), "r"(a3), "r"(b0), "r"(b1));
}

__global__ void __launch_bounds__(256, 2)
block_mma(const float* __restrict__ Xg, const float* __restrict__ Wattn,
          const float* __restrict__ Wproj, const float* __restrict__ Wff1,
          const float* __restrict__ Wff2, float* __restrict__ Out, int nwt)
{
    extern __shared__ char smc[];
    __nv_bfloat16* wsm = (__nv_bfloat16*)smc;
    const int tid = threadIdx.x;

    // ---- stage weights: [n][k] bf16, row strides 40 / 136 bf16 ----
    for (int i = tid; i < 96 * 32; i += 256) {           // QKV: n = h*24 + d (K,Q,V order)
        int n = i >> 5, k = i & 31;
        int h = n / 24, d = n - h * 24;
        wsm[(OFF_WQ >> 1) + n * 40 + k] = __float2bfloat16(Wattn[h * 768 + k * 24 + d]);
    }
    for (int i = tid; i < 32 * 32; i += 256) {
        int n = i >> 5, k = i & 31;
        wsm[(OFF_WP >> 1) + n * 40 + k] = __float2bfloat16(Wproj[k * 32 + n]);
    }
    for (int i = tid; i < 128 * 32; i += 256) {
        int n = i >> 5, k = i & 31;
        wsm[(OFF_W1 >> 1) + n * 40 + k] = __float2bfloat16(Wff1[k * 128 + n]);
    }
    for (int i = tid; i < 32 * 128; i += 256) {
        int n = i & 31, k = i >> 5;                      // coalesced gmem read on n
        wsm[(OFF_W2 >> 1) + n * 136 + k] = __float2bfloat16(Wff2[k * 32 + n]);
    }
    __syncthreads();

    const uint32_t* wqU = (const uint32_t*)(smc + OFF_WQ);   // word stride 20
    const uint32_t* wpU = (const uint32_t*)(smc + OFF_WP);
    const uint32_t* w1U = (const uint32_t*)(smc + OFF_W1);
    const uint32_t* w2U = (const uint32_t*)(smc + OFF_W2);   // word stride 68

    const int warp = tid >> 5, lane = tid & 31;
    float*    qkvS = (float*)(smc + OFF_WARP + warp * WARP_BYTES);          // [16][100] f32
    uint32_t* attU = (uint32_t*)(smc + OFF_WARP + warp * WARP_BYTES + 6400); // [16][20] words

    const int g = lane >> 2, t = lane & 3;     // fragment coords
    const int h = lane >> 3, t1 = lane & 7;    // attention coords
    const float scale = 0.17677669529663687f;  // 32^-0.5

    const int gw = (blockIdx.x << 3) + warp;
    const int stride = gridDim.x << 3;

    for (int wt = gw; wt < nwt; wt += stride) {
        const float* Xi = Xg + (size_t)wt * 512;

        // ---- load X in fragment layout: rows g, g+8 ; col pairs 2t+8j ----
        float2 xg[4], xh[4];
        #pragma unroll
        for (int j = 0; j < 4; j++) {
            xg[j] = *(const float2*)(Xi + g * 32 + 2 * t + 8 * j);
            xh[j] = *(const float2*)(Xi + (g + 8) * 32 + 2 * t + 8 * j);
        }
        uint32_t ag[4], ah[4];
        #pragma unroll
        for (int j = 0; j < 4; j++) {
            ag[j] = cvt_bf2(xg[j].x, xg[j].y);
            ah[j] = cvt_bf2(xh[j].x, xh[j].y);
        }

        // ---- QKV: X(16x32) @ Wqkv(32x96) -> qkv smem tile ----
        #pragma unroll
        for (int nt = 0; nt < 12; nt++) {
            float d0 = 0.f, d1 = 0.f, d2 = 0.f, d3 = 0.f;
            #pragma unroll
            for (int kt = 0; kt < 2; kt++) {
                uint32_t base = (8 * nt + g) * 20 + t + 8 * kt;
                mma16816(d0, d1, d2, d3,
                         ag[2*kt], ah[2*kt], ag[2*kt+1], ah[2*kt+1],
                         wqU[base], wqU[base + 4]);
            }
            *(float2*)(qkvS + g * 100 + 8 * nt + 2 * t)       = make_float2(d0, d1);
            *(float2*)(qkvS + (g + 8) * 100 + 8 * nt + 2 * t) = make_float2(d2, d3);
        }
        __syncwarp();

        // ---- attention (2 items), lane = (h, t1) ----
        #pragma unroll
        for (int it = 0; it < 2; it++) {
            const float* bp = qkvS + it * 800 + h * 24;
            float4 q0 = *(const float4*)(bp + t1 * 100 + 8);
            float4 q1 = *(const float4*)(bp + t1 * 100 + 12);
            float s[8], m = -1e30f;
            #pragma unroll
            for (int t2 = 0; t2 < 8; t2++) {
                float4 k0 = *(const float4*)(bp + t2 * 100);
                float4 k1 = *(const float4*)(bp + t2 * 100 + 4);
                float d = q0.x*k0.x + q0.y*k0.y + q0.z*k0.z + q0.w*k0.w
                        + q1.x*k1.x + q1.y*k1.y + q1.z*k1.z + q1.w*k1.w;
                d *= scale;
                d = (t2 <= t1) ? d : -1e30f;
                s[t2] = d; m = fmaxf(m, d);
            }
            float sum = 0.f;
            #pragma unroll
            for (int t2 = 0; t2 < 8; t2++) {
                float e = (t2 <= t1) ? __expf(s[t2] - m) : 0.f;
                s[t2] = e; sum += e;
            }
            float inv = __fdividef(1.f, sum);
            float a[8];
            #pragma unroll
            for (int d = 0; d < 8; d++) a[d] = 0.f;
            #pragma unroll
            for (int t2 = 0; t2 < 8; t2++) {
                float w = s[t2];
                float4 v0 = *(const float4*)(bp + t2 * 100 + 16);
                float4 v1 = *(const float4*)(bp + t2 * 100 + 20);
                a[0] = fmaf(w, v0.x, a[0]); a[1] = fmaf(w, v0.y, a[1]);
                a[2] = fmaf(w, v0.z, a[2]); a[3] = fmaf(w, v0.w, a[3]);
                a[4] = fmaf(w, v1.x, a[4]); a[5] = fmaf(w, v1.y, a[5]);
                a[6] = fmaf(w, v1.z, a[6]); a[7] = fmaf(w, v1.w, a[7]);
            }
            int row = it * 8 + t1;
            #pragma unroll
            for (int j = 0; j < 4; j++)
                attU[row * 20 + h * 4 + j] = cvt_bf2(a[2*j] * inv, a[2*j+1] * inv);
        }
        __syncwarp();

        // ---- proj + residual: Y = X + attn @ Wproj (regs, frag layout) ----
        float2 yg[4], yh[4];
        {
            uint32_t pa[2][4];
            #pragma unroll
            for (int kt = 0; kt < 2; kt++) {
                uint32_t b = g * 20 + t + 8 * kt;
                pa[kt][0] = attU[b];            pa[kt][1] = attU[b + 160];     // (g+8)*20
                pa[kt][2] = attU[b + 4];        pa[kt][3] = attU[b + 164];
            }
            #pragma unroll
            for (int nt = 0; nt < 4; nt++) {
                float d0 = 0.f, d1 = 0.f, d2 = 0.f, d3 = 0.f;
                #pragma unroll
                for (int kt = 0; kt < 2; kt++) {
                    uint32_t base = (8 * nt + g) * 20 + t + 8 * kt;
                    mma16816(d0, d1, d2, d3,
                             pa[kt][0], pa[kt][1], pa[kt][2], pa[kt][3],
                             wpU[base], wpU[base + 4]);
                }
                yg[nt] = make_float2(xg[nt].x + d0, xg[nt].y + d1);
                yh[nt] = make_float2(xh[nt].x + d2, xh[nt].y + d3);
            }
        }
        uint32_t yag[4], yah[4];
        #pragma unroll
        for (int j = 0; j < 4; j++) {
            yag[j] = cvt_bf2(yg[j].x, yg[j].y);
            yah[j] = cvt_bf2(yh[j].x, yh[j].y);
        }

        // ---- FF1: H = relu(Y @ W1) -> bf16 frags in regs (two N=64 halves) ----
        uint32_t hg[16], hh[16];
        #pragma unroll
        for (int half = 0; half < 2; half++) {
            #pragma unroll
            for (int q = 0; q < 8; q++) {
                int nt = half * 8 + q;
                float d0 = 0.f, d1 = 0.f, d2 = 0.f, d3 = 0.f;
                #pragma unroll
                for (int kt = 0; kt < 2; kt++) {
                    uint32_t base = (8 * nt + g) * 20 + t + 8 * kt;
                    mma16816(d0, d1, d2, d3,
                             yag[2*kt], yah[2*kt], yag[2*kt+1], yah[2*kt+1],
                             w1U[base], w1U[base + 4]);
                }
                hg[nt] = cvt_bf2(fmaxf(d0, 0.f), fmaxf(d1, 0.f));
                hh[nt] = cvt_bf2(fmaxf(d2, 0.f), fmaxf(d3, 0.f));
            }
        }

        // ---- FF2 + residual + store: out = Y + H @ W2 ----
        float* Og = Out + (size_t)wt * 512;
        #pragma unroll
        for (int nt = 0; nt < 4; nt++) {
            float d0 = 0.f, d1 = 0.f, d2 = 0.f, d3 = 0.f;
            #pragma unroll
            for (int kt = 0; kt < 8; kt++) {
                uint32_t base = (8 * nt + g) * 68 + t + 8 * kt;
                mma16816(d0, d1, d2, d3,
                         hg[2*kt], hh[2*kt], hg[2*kt+1], hh[2*kt+1],
                         w2U[base], w2U[base + 4]);
            }
            *(float2*)(Og + g * 32 + 2 * t + 8 * nt)       = make_float2(yg[nt].x + d0, yg[nt].y + d1);
            *(float2*)(Og + (g + 8) * 32 + 2 * t + 8 * nt) = make_float2(yh[nt].x + d2, yh[nt].y + d3);
        }
        __syncwarp();   // per-warp smem reused next iteration
    }
}

extern "C" void kernel_launch(void* const* d_in, const int* in_sizes, int n_in,
                              void* d_out, int out_size) {
    const float* X     = (const float*)d_in[0];
    const float* Wattn = (const float*)d_in[1];
    const float* Wproj = (const float*)d_in[2];
    const float* Wff1  = (const float*)d_in[3];
    const float* Wff2  = (const float*)d_in[4];
    float* out = (float*)d_out;

    int nwt = in_sizes[0] / 512;    // 16-token warp tiles
    int sms = 148;
    cudaDeviceGetAttribute(&sms, cudaDevAttrMultiProcessorCount, 0);
    int grid = 2 * sms;             // persistent, 2 CTAs/SM
    int maxg = (nwt + 7) / 8;
    if (grid > maxg) grid = maxg;

    cudaFuncSetAttribute(block_mma, cudaFuncAttributeMaxDynamicSharedMemorySize, SMEM_BYTES);
    block_mma<<<grid, 256, SMEM_BYTES>>>(X, Wattn, Wproj, Wff1, Wff2, out, nwt);
    (void)n_in; (void)out_size;
}

// round 5
// speedup vs baseline: 12.5580x; 1.4595x over previous
#include <cuda_runtime.h>
#include <cuda_bf16.h>
#include <cstdint>

// Transformer block, fully tensor-core: QKV/proj/FF1/FF2 AND attention
// (S=Q K^T, O=P V) via mma.sync m16n8k16 bf16. One warp = 16 tokens (2 items).
// No per-warp smem, no barriers in the main loop. Weights live in smem
// pre-packed in per-lane fragment order (LDS.128 per B tile).

// smem word offsets (uint32 words)
#define QKVF 0        // [12 nt][32 lane][4 w] = 1536 words
#define PF   1536     // [4][32][4]  = 512
#define F1F  2048     // [16][32][4] = 2048
#define F2F  4096     // [4 nt][4 grp][32][4] = 2048
#define SMEM_WORDS 6144   // 24 KB

static __device__ __forceinline__ uint32_t cvt_bf2(float lo, float hi) {
    uint32_t r;
    asm("cvt.rn.bf16x2.f32 %0, %1, %2;" : "=r"(r) : "f"(hi), "f"(lo));
    return r;
}
static __device__ __forceinline__ uint32_t prmt(uint32_t a, uint32_t b, uint32_t sel) {
    uint32_t r;
    asm("prmt.b32 %0, %1, %2, %3;" : "=r"(r) : "r"(a), "r"(b), "r"(sel));
    return r;
}
static __device__ __forceinline__ void mma16816(float& d0, float& d1, float& d2, float& d3,
                                                uint32_t a0, uint32_t a1, uint32_t a2, uint32_t a3,
                                                uint32_t b0, uint32_t b1) {
    asm volatile("mma.sync.aligned.m16n8k16.row.col.f32.bf16.bf16.f32 "
                 "{%0,%1,%2,%3}, {%4,%5,%6,%7}, {%8,%9}, {%0,%1,%2,%3};"
                 : "+f"(d0), "+f"(d1), "+f"(d2), "+f"(d3)
                 : "r"(a0), "r"(a1), "r"(a2), "r"(a3), "r"(b0), "r"(b1));
}

__global__ void __launch_bounds__(256, 2)
block_mma2(const float* __restrict__ Xg, const float* __restrict__ Wattn,
           const float* __restrict__ Wproj, const float* __restrict__ Wff1,
           const float* __restrict__ Wff2, float* __restrict__ Out, int nwt)
{
    extern __shared__ uint32_t wsm[];
    const int tid = threadIdx.x;

    // ---- stage weights in fragment-packed order ----
    // word(nt,lane,w) = pack(W[k0][n], W[k0+1][n]), n = 8*nt+g, k0 = 8w+2t
    for (int i = tid; i < 1536; i += 256) {             // QKV (n = h*24+d, K|Q|V)
        int w = i & 3, lane = (i >> 2) & 31, nt = i >> 7;
        int g = lane >> 2, t = lane & 3;
        int n = 8 * nt + g, k0 = 8 * w + 2 * t;
        int h = n / 24, d = n - 24 * h;
        wsm[QKVF + i] = cvt_bf2(Wattn[h * 768 + k0 * 24 + d],
                                Wattn[h * 768 + (k0 + 1) * 24 + d]);
    }
    for (int i = tid; i < 512; i += 256) {              // proj
        int w = i & 3, lane = (i >> 2) & 31, nt = i >> 7;
        int g = lane >> 2, t = lane & 3;
        int n = 8 * nt + g, k0 = 8 * w + 2 * t;
        wsm[PF + i] = cvt_bf2(Wproj[k0 * 32 + n], Wproj[(k0 + 1) * 32 + n]);
    }
    for (int i = tid; i < 2048; i += 256) {             // ff1
        int w = i & 3, lane = (i >> 2) & 31, nt = i >> 7;
        int g = lane >> 2, t = lane & 3;
        int n = 8 * nt + g, k0 = 8 * w + 2 * t;
        wsm[F1F + i] = cvt_bf2(Wff1[k0 * 128 + n], Wff1[(k0 + 1) * 128 + n]);
    }
    for (int i = tid; i < 2048; i += 256) {             // ff2: k=128, [nt][grp][lane][w]
        int w = i & 3, lane = (i >> 2) & 31, grp = (i >> 7) & 3, nt = i >> 9;
        int g = lane >> 2, t = lane & 3;
        int n = 8 * nt + g;
        int k0 = 16 * (2 * grp + (w >> 1)) + 2 * t + 8 * (w & 1);
        wsm[F2F + i] = cvt_bf2(Wff2[k0 * 32 + n], Wff2[(k0 + 1) * 32 + n]);
    }
    __syncthreads();

    const int warp = tid >> 5, lane = tid & 31;
    const int g = lane >> 2, t = lane & 3;
    const uint32_t psel = (g & 1) ? 0x7632u : 0x5410u;
    const int src0 = 8 * t + (g >> 1);
    const bool v0 = (2 * t     <= g);
    const bool v1 = (2 * t + 1 <= g);
    const float scale = 0.17677669529663687f;   // 32^-0.5 (full embed dim, per ref)
    const uint32_t Z = 0;

    const int gw = (blockIdx.x << 3) + warp;
    const int stride = gridDim.x << 3;

    for (int wt = gw; wt < nwt; wt += stride) {
        const float* Xi = Xg + (size_t)wt * 512;

        // ---- X in fragment layout ----
        float2 xg[4], xh[4];
        #pragma unroll
        for (int j = 0; j < 4; j++) {
            xg[j] = *(const float2*)(Xi + g * 32 + 2 * t + 8 * j);
            xh[j] = *(const float2*)(Xi + (g + 8) * 32 + 2 * t + 8 * j);
        }
        uint32_t ag[4], ah[4];
        #pragma unroll
        for (int j = 0; j < 4; j++) {
            ag[j] = cvt_bf2(xg[j].x, xg[j].y);
            ah[j] = cvt_bf2(xh[j].x, xh[j].y);
        }

        // ---- per-head: QKV mma + full attention in registers ----
        uint32_t o01[4], o23[4];
        #pragma unroll
        for (int h = 0; h < 4; h++) {
            uint4 Bk = *(const uint4*)(wsm + QKVF + ((3 * h    ) * 32 + lane) * 4);
            uint4 Bq = *(const uint4*)(wsm + QKVF + ((3 * h + 1) * 32 + lane) * 4);
            uint4 Bv = *(const uint4*)(wsm + QKVF + ((3 * h + 2) * 32 + lane) * 4);

            float kd0=0,kd1=0,kd2=0,kd3=0, qd0=0,qd1=0,qd2=0,qd3=0, vd0=0,vd1=0,vd2=0,vd3=0;
            mma16816(kd0,kd1,kd2,kd3, ag[0],ah[0],ag[1],ah[1], Bk.x,Bk.y);
            mma16816(kd0,kd1,kd2,kd3, ag[2],ah[2],ag[3],ah[3], Bk.z,Bk.w);
            mma16816(qd0,qd1,qd2,qd3, ag[0],ah[0],ag[1],ah[1], Bq.x,Bq.y);
            mma16816(qd0,qd1,qd2,qd3, ag[2],ah[2],ag[3],ah[3], Bq.z,Bq.w);
            mma16816(vd0,vd1,vd2,vd3, ag[0],ah[0],ag[1],ah[1], Bv.x,Bv.y);
            mma16816(vd0,vd1,vd2,vd3, ag[2],ah[2],ag[3],ah[3], Bv.z,Bv.w);

            // S = Q K^T, both items in one mma (item0 k-slots 0-7, item1 8-15)
            uint32_t bk0 = cvt_bf2(kd0, kd1), bk1 = cvt_bf2(kd2, kd3);
            uint32_t aq0 = cvt_bf2(qd0, qd1), aq3 = cvt_bf2(qd2, qd3);
            float s0=0,s1=0,s2=0,s3=0;
            mma16816(s0,s1,s2,s3, aq0, Z, Z, aq3, bk0, bk1);
            s0 *= scale; s1 *= scale; s2 *= scale; s3 *= scale;

            // softmax (quad = 4 lanes holding query g's 8 scores), causal mask
            float m0 = fmaxf(v0 ? s0 : -1e30f, v1 ? s1 : -1e30f);
            m0 = fmaxf(m0, __shfl_xor_sync(0xffffffffu, m0, 1));
            m0 = fmaxf(m0, __shfl_xor_sync(0xffffffffu, m0, 2));
            float p0 = v0 ? __expf(s0 - m0) : 0.f;
            float p1 = v1 ? __expf(s1 - m0) : 0.f;
            float r0 = p0 + p1;
            r0 += __shfl_xor_sync(0xffffffffu, r0, 1);
            r0 += __shfl_xor_sync(0xffffffffu, r0, 2);
            float i0 = __fdividef(1.f, r0);

            float m1 = fmaxf(v0 ? s2 : -1e30f, v1 ? s3 : -1e30f);
            m1 = fmaxf(m1, __shfl_xor_sync(0xffffffffu, m1, 1));
            m1 = fmaxf(m1, __shfl_xor_sync(0xffffffffu, m1, 2));
            float p2 = v0 ? __expf(s2 - m1) : 0.f;
            float p3 = v1 ? __expf(s3 - m1) : 0.f;
            float r1 = p2 + p3;
            r1 += __shfl_xor_sync(0xffffffffu, r1, 1);
            r1 += __shfl_xor_sync(0xffffffffu, r1, 2);
            float i1 = __fdividef(1.f, r1);

            uint32_t aP0 = cvt_bf2(p0 * i0, p1 * i0);
            uint32_t aP3 = cvt_bf2(p2 * i1, p3 * i1);

            // V^T fragments via shuffle (b0 = V0[2t..][g], b1 = V1[2t..][g])
            uint32_t pv01 = cvt_bf2(vd0, vd1), pv23 = cvt_bf2(vd2, vd3);
            uint32_t u0 = __shfl_sync(0xffffffffu, pv01, src0);
            uint32_t u1 = __shfl_sync(0xffffffffu, pv01, src0 + 4);
            uint32_t bv0 = prmt(u0, u1, psel);
            uint32_t w0 = __shfl_sync(0xffffffffu, pv23, src0);
            uint32_t w1 = __shfl_sync(0xffffffffu, pv23, src0 + 4);
            uint32_t bv1 = prmt(w0, w1, psel);

            // O = P V (item0 rows g via slots 0-7, item1 rows g+8 via slots 8-15)
            float od0=0,od1=0,od2=0,od3=0;
            mma16816(od0,od1,od2,od3, aP0, Z, Z, aP3, bv0, bv1);
            o01[h] = cvt_bf2(od0, od1);
            o23[h] = cvt_bf2(od2, od3);
        }

        // ---- proj + residual: Y = X + O @ Wproj ----
        float2 yg[4], yh[4];
        #pragma unroll
        for (int nt = 0; nt < 4; nt++) {
            uint4 Bp = *(const uint4*)(wsm + PF + (nt * 32 + lane) * 4);
            float d0=0,d1=0,d2=0,d3=0;
            mma16816(d0,d1,d2,d3, o01[0],o23[0],o01[1],o23[1], Bp.x,Bp.y);   // heads 0,1 = k 0-15
            mma16816(d0,d1,d2,d3, o01[2],o23[2],o01[3],o23[3], Bp.z,Bp.w);   // heads 2,3 = k 16-31
            yg[nt] = make_float2(xg[nt].x + d0, xg[nt].y + d1);
            yh[nt] = make_float2(xh[nt].x + d2, xh[nt].y + d3);
        }
        uint32_t ya[4], yb[4];
        #pragma unroll
        for (int j = 0; j < 4; j++) {
            ya[j] = cvt_bf2(yg[j].x, yg[j].y);
            yb[j] = cvt_bf2(yh[j].x, yh[j].y);
        }

        // ---- FF1: H = relu(Y @ W1) ----
        uint32_t hg[16], hh[16];
        #pragma unroll
        for (int nt = 0; nt < 16; nt++) {
            uint4 B1 = *(const uint4*)(wsm + F1F + (nt * 32 + lane) * 4);
            float d0=0,d1=0,d2=0,d3=0;
            mma16816(d0,d1,d2,d3, ya[0],yb[0],ya[1],yb[1], B1.x,B1.y);
            mma16816(d0,d1,d2,d3, ya[2],yb[2],ya[3],yb[3], B1.z,B1.w);
            hg[nt] = cvt_bf2(fmaxf(d0, 0.f), fmaxf(d1, 0.f));
            hh[nt] = cvt_bf2(fmaxf(d2, 0.f), fmaxf(d3, 0.f));
        }

        // ---- FF2 + residual + store ----
        float* Og = Out + (size_t)wt * 512;
        #pragma unroll
        for (int nt = 0; nt < 4; nt++) {
            float d0=0,d1=0,d2=0,d3=0;
            #pragma unroll
            for (int grp = 0; grp < 4; grp++) {
                uint4 B2 = *(const uint4*)(wsm + F2F + ((nt * 4 + grp) * 32 + lane) * 4);
                mma16816(d0,d1,d2,d3, hg[4*grp  ],hh[4*grp  ],hg[4*grp+1],hh[4*grp+1], B2.x,B2.y);
                mma16816(d0,d1,d2,d3, hg[4*grp+2],hh[4*grp+2],hg[4*grp+3],hh[4*grp+3], B2.z,B2.w);
            }
            *(float2*)(Og + g * 32 + 2 * t + 8 * nt)       = make_float2(yg[nt].x + d0, yg[nt].y + d1);
            *(float2*)(Og + (g + 8) * 32 + 2 * t + 8 * nt) = make_float2(yh[nt].x + d2, yh[nt].y + d3);
        }
    }
}

extern "C" void kernel_launch(void* const* d_in, const int* in_sizes, int n_in,
                              void* d_out, int out_size) {
    const float* X     = (const float*)d_in[0];
    const float* Wattn = (const float*)d_in[1];
    const float* Wproj = (const float*)d_in[2];
    const float* Wff1  = (const float*)d_in[3];
    const float* Wff2  = (const float*)d_in[4];
    float* out = (float*)d_out;

    int nwt = in_sizes[0] / 512;    // 16-token warp tiles
    int sms = 148;
    cudaDeviceGetAttribute(&sms, cudaDevAttrMultiProcessorCount, 0);
    int grid = 2 * sms;
    int maxg = (nwt + 7) / 8;
    if (grid > maxg) grid = maxg;

    block_mma2<<<grid, 256, SMEM_WORDS * 4>>>(X, Wattn, Wproj, Wff1, Wff2, out, nwt);
    (void)n_in; (void)out_size;
}